// round 7
// baseline (speedup 1.0000x reference)
#include <cuda_runtime.h>
#include <cuda_bf16.h>
#include <stdint.h>
#include <math.h>

// ---------------------------------------------------------------------------
// 2-bit quantized CNN forward.
//  conv1: fp32 conv via packed fma.rn.f32x2
//  conv2/conv3: hybrid warp-specialized int8 conv:
//    warps 0-3: mma.sync.m16n8k32.s8 (tensor pipe) for 40/64 channels
//    warps 4-7: dp4a (alu pipe) for 24/64 channels, LDS.128 conflict-free
//  Exact integer math: conv = (sum code*wint) * (alpha_prev/3 * s_w).
// ---------------------------------------------------------------------------

__device__ unsigned g_smax[4];                 // maxabs bits: w1, wc, w2, w3
__device__ float    g_qw1[32 * 3 * 9];
__device__ float    g_qwc[10 * 128];
__device__ int      g_wf2[9 * 64 * 8];         // mma B-frags [tap][oc][p]
__device__ int      g_wf3[9 * 2 * 128 * 8];    // [tap][chunk][oc][p]
__device__ uint4    g_dw2[8 * 9 * 6];          // dp4a w [k][tap][oc4] (oc40..63)
__device__ uint4    g_dw3[2 * 16 * 9 * 6];     // [z][k][tap][oc4]
__device__ uint8_t  g_c1[32L * 112 * 112 * 32];
__device__ uint8_t  g_c2[32L * 56 * 56 * 64];
__device__ uint8_t  g_c3[32L * 28 * 28 * 128];

// ---- helpers ---------------------------------------------------------------
__device__ __forceinline__ uint32_t smem_u32(const void* p) {
    uint32_t a;
    asm("{ .reg .u64 t; cvta.to.shared.u64 t, %1; cvt.u32.u64 %0, t; }"
        : "=r"(a) : "l"(p));
    return a;
}
__device__ __forceinline__ void ldsm4(uint32_t addr, int& a0, int& a1,
                                      int& a2, int& a3) {
    asm volatile("ldmatrix.sync.aligned.m8n8.x4.shared.b16 {%0,%1,%2,%3},[%4];"
                 : "=r"(a0), "=r"(a1), "=r"(a2), "=r"(a3) : "r"(addr));
}
__device__ __forceinline__ void mma_s8(int* d, int a0, int a1, int a2, int a3,
                                       int b0, int b1) {
    asm("mma.sync.aligned.m16n8k32.row.col.s32.s8.s8.s32 "
        "{%0,%1,%2,%3},{%4,%5,%6,%7},{%8,%9},{%0,%1,%2,%3};"
        : "+r"(d[0]), "+r"(d[1]), "+r"(d[2]), "+r"(d[3])
        : "r"(a0), "r"(a1), "r"(a2), "r"(a3), "r"(b0), "r"(b1));
}
#define PACK_F32X2(out, lo, hi) \
    asm("mov.b64 %0, {%1, %2};" : "=l"(out) : "r"(lo), "r"(hi))
#define UNPACK_F32X2(lo, hi, in) \
    asm("mov.b64 {%0, %1}, %2;" : "=f"(lo), "=f"(hi) : "l"(in))
#define FMA_F32X2(acc, a, b) \
    asm("fma.rn.f32x2 %0, %1, %2, %0;" : "+l"(acc) : "l"(a), "l"(b))

__device__ __forceinline__ float get_scale(int t) {
    return fmaxf(__uint_as_float(g_smax[t]), 1e-8f);
}

// ---- prologue 1: max|w| -----------------------------------------------------
__global__ void maxabs_kernel(const float* __restrict__ w1,
                              const float* __restrict__ wc,
                              const float* __restrict__ w2,
                              const float* __restrict__ w3) {
    __shared__ float red[8];
    const int blk = blockIdx.x;
    int t, base, cnt;
    const float* p;
    if (blk == 0)      { t = 0; p = w1; base = 0; cnt = 864; }
    else if (blk == 1) { t = 1; p = wc; base = 0; cnt = 1280; }
    else if (blk < 6)  { t = 2; p = w2; base = (blk - 2) * 4608; cnt = 4608; }
    else               { t = 3; p = w3; base = (blk - 6) * 4608; cnt = 4608; }
    float m = 0.f;
    for (int i = threadIdx.x; i < cnt; i += 256)
        m = fmaxf(m, fabsf(p[base + i]));
    #pragma unroll
    for (int o = 16; o; o >>= 1)
        m = fmaxf(m, __shfl_xor_sync(0xffffffffu, m, o));
    if ((threadIdx.x & 31) == 0) red[threadIdx.x >> 5] = m;
    __syncthreads();
    if (threadIdx.x == 0) {
        float v = red[0];
        #pragma unroll
        for (int i = 1; i < 8; i++) v = fmaxf(v, red[i]);
        atomicMax(&g_smax[t], __float_as_uint(v));  // |w|>=0, bit-monotone
    }
}

// ---- prologue 2: quantize + pack --------------------------------------------
__global__ void pack_kernel(const float* __restrict__ w1,
                            const float* __restrict__ wc,
                            const float* __restrict__ w2,
                            const float* __restrict__ w3) {
    const int blk = blockIdx.x;
    if (blk == 0) {
        const float s = get_scale(0);
        for (int i = threadIdx.x; i < 864; i += 256)
            g_qw1[i] = rintf(w1[i] / s) * s;
    } else if (blk == 1) {
        const float s = get_scale(1);
        for (int i = threadIdx.x; i < 1280; i += 256)
            g_qwc[i] = rintf(wc[i] / s) * s;
    } else if (blk == 2) {
        // mma frags conv2: word p: icw = (p>>1) + (p&1)*4
        const float inv_s = 1.f / get_scale(2);
        for (int i = threadIdx.x; i < 9 * 64 * 8; i += 256) {
            const int tap = i / 512, r = i % 512, oc = r >> 3, p = r & 7;
            const int icw = (p >> 1) + ((p & 1) << 2);
            uint32_t word = 0;
            #pragma unroll
            for (int l = 0; l < 4; l++) {
                const int ic = icw * 4 + l;
                const int c = (int)rintf(w2[(oc * 32 + ic) * 9 + tap] * inv_s);
                word |= ((uint32_t)(uint8_t)(int8_t)c) << (8 * l);
            }
            g_wf2[i] = (int)word;
        }
    } else if (blk == 3) {
        const float inv_s = 1.f / get_scale(3);
        for (int i = threadIdx.x; i < 9 * 2 * 128 * 8; i += 256) {
            const int tap = i / 2048, r = i % 2048;
            const int chunk = r >> 10, r2 = r & 1023, oc = r2 >> 3, p = r2 & 7;
            const int icw = (p >> 1) + ((p & 1) << 2);
            uint32_t word = 0;
            #pragma unroll
            for (int l = 0; l < 4; l++) {
                const int ic = chunk * 32 + (icw * 4) + l;
                const int c = (int)rintf(w3[(oc * 64 + ic) * 9 + tap] * inv_s);
                word |= ((uint32_t)(uint8_t)(int8_t)c) << (8 * l);
            }
            g_wf3[i] = (int)word;
        }
    } else if (blk == 4) {
        // dp4a conv2 weights: oc 40..63, [k][tap][d] u32 words
        const float inv_s = 1.f / get_scale(2);
        uint32_t* dst = (uint32_t*)g_dw2;
        for (int i = threadIdx.x; i < 8 * 9 * 24; i += 256) {
            const int k = i / 216, t = (i % 216) / 24, d = i % 24;
            const int oc = 40 + d;
            uint32_t word = 0;
            #pragma unroll
            for (int l = 0; l < 4; l++) {
                const int ic = k * 4 + l;
                const int c = (int)rintf(w2[(oc * 32 + ic) * 9 + t] * inv_s);
                word |= ((uint32_t)(uint8_t)(int8_t)c) << (8 * l);
            }
            dst[i] = word;
        }
    } else {
        // dp4a conv3 weights: z in {0,1}, oc z*64+40..+63
        const float inv_s = 1.f / get_scale(3);
        uint32_t* dst = (uint32_t*)g_dw3;
        for (int i = threadIdx.x; i < 2 * 16 * 9 * 24; i += 256) {
            const int z = i / 3456, r = i % 3456;
            const int k = r / 216, t = (r % 216) / 24, d = r % 24;
            const int oc = z * 64 + 40 + d;
            uint32_t word = 0;
            #pragma unroll
            for (int l = 0; l < 4; l++) {
                const int ic = k * 4 + l;
                const int c = (int)rintf(w3[(oc * 64 + ic) * 9 + t] * inv_s);
                word |= ((uint32_t)(uint8_t)(int8_t)c) << (8 * l);
            }
            dst[i] = word;
        }
    }
}

// ---- block 1: fp32 conv3x3(pad1) via fma.f32x2 + quant_act + maxpool2 -------
__global__ __launch_bounds__(128) void conv1_kernel(
    const float* __restrict__ x, const float* __restrict__ alpha_p,
    uint8_t* __restrict__ out) {
    constexpr int H = 224, W = 224, PH = 112, PW = 112, OC = 32, OCB = 8;
    __shared__ float sx[3][18][34];
    __shared__ unsigned long long swp[OCB][3][9];   // (w,w) duplicated pairs

    const int tid = threadIdx.x;
    const int tx = tid & 15, ty = tid >> 4;
    const int tile_x = blockIdx.x;
    const int tile_y = blockIdx.y % 14;
    const int b      = blockIdx.y / 14;
    const int oc0    = blockIdx.z * OCB;

    const int px0 = tile_x * 16, py0 = tile_y * 8;
    const int ix0 = 2 * px0 - 1, iy0 = 2 * py0 - 1;

    const float* xb = x + (long)b * 3 * H * W;
    for (int i = tid; i < 3 * 18 * 34; i += 128) {
        const int ic = i / 612, rr = (i % 612) / 34, cc = i % 34;
        const int gy = iy0 + rr, gx = ix0 + cc;
        float v = 0.f;
        if (gy >= 0 && gy < H && gx >= 0 && gx < W)
            v = xb[(long)ic * H * W + gy * W + gx];
        sx[ic][rr][cc] = v;
    }
    if (tid < OCB * 27) {
        const int j = tid / 27, r27 = tid % 27;
        const float w = g_qw1[((oc0 + j) * 3 + r27 / 9) * 9 + r27 % 9];
        unsigned long long pw;
        PACK_F32X2(pw, __float_as_uint(w), __float_as_uint(w));
        swp[j][r27 / 9][r27 % 9] = pw;
    }
    __syncthreads();

    unsigned long long accA[OCB], accB[OCB];
    #pragma unroll
    for (int j = 0; j < OCB; j++) { accA[j] = 0ull; accB[j] = 0ull; }

    #pragma unroll
    for (int ic = 0; ic < 3; ic++) {
        float win[4][4];
        #pragma unroll
        for (int r = 0; r < 4; r++)
            #pragma unroll
            for (int c = 0; c < 4; c++)
                win[r][c] = sx[ic][2 * ty + r][2 * tx + c];
        unsigned long long pk[4][3];
        #pragma unroll
        for (int r = 0; r < 4; r++)
            #pragma unroll
            for (int c = 0; c < 3; c++)
                PACK_F32X2(pk[r][c], __float_as_uint(win[r][c]),
                           __float_as_uint(win[r][c + 1]));
        #pragma unroll
        for (int j = 0; j < OCB; j++) {
            #pragma unroll
            for (int ky = 0; ky < 3; ky++)
                #pragma unroll
                for (int kx = 0; kx < 3; kx++) {
                    FMA_F32X2(accA[j], pk[ky][kx], swp[j][ic][ky * 3 + kx]);
                    FMA_F32X2(accB[j], pk[ky + 1][kx], swp[j][ic][ky * 3 + kx]);
                }
        }
    }

    const float alpha = __ldg(alpha_p);
    const float inv_scale = 3.f / alpha;
    const int px = px0 + tx, py = py0 + ty;
    uint32_t lo = 0, hi = 0;
    #pragma unroll
    for (int j = 0; j < OCB; j++) {
        float p0, p1, p2, p3;
        UNPACK_F32X2(p0, p1, accA[j]);
        UNPACK_F32X2(p2, p3, accB[j]);
        const float m = fmaxf(fmaxf(p0, p1), fmaxf(p2, p3));
        const float y = fminf(fmaxf(m, 0.f), alpha);
        const uint32_t code = (uint32_t)(int)rintf(y * inv_scale);
        if (j < 4) lo |= code << (8 * j);
        else       hi |= code << (8 * (j - 4));
    }
    *(uint2*)&out[(((long)b * PH + py) * PW + px) * OC + oc0] = make_uint2(lo, hi);
}

// ---- blocks 2/3: hybrid mma+dp4a conv + quant_act + maxpool2 ----------------
// 8 warps: warps 0-3 = mma (MMAOC channels), warps 4-7 = dp4a (DPOC channels).
// dp4a activation loads are LDS.128 (uint4, 4 k-words), conflict-free at
// PSTRIDE=48/80 (8-lane phase banks all distinct).
template <int H, int IC, int OC, int NOC, int MMAOC, int TW, int TH, int PSTRIDE>
__global__ __launch_bounds__(256) void conv_hyb(
    const uint8_t* __restrict__ xin, const int* __restrict__ wf,
    const uint4* __restrict__ dw,
    const float* __restrict__ aprev_p, const float* __restrict__ acur_p,
    int wtensor, uint8_t* __restrict__ out) {
    constexpr int DPOC = NOC - MMAOC;          // 24
    constexpr int DQ   = DPOC / 4;             // 6
    constexpr int CH   = IC / 32;
    constexpr int IC4  = IC / 4;
    constexpr int IC16 = IC / 16;              // uint4 k-groups
    constexpr int TIW  = TW + 2, TIH = TH + 2;
    constexpr int OCG  = MMAOC / 8;            // 5
    constexpr int VPP  = IC / 16;
    constexpr int WTX  = TW / 8, WTY = TH / 2, NWT = WTX * WTY;
    constexpr int PHW  = H / 2;
    constexpr int DLANES = TW * (TH / 2);

    extern __shared__ __align__(16) uint8_t dsm[];
    uint8_t* stile = dsm;                                   // TIH*TIW*PSTRIDE
    uint4*   sdw   = (uint4*)(dsm + TIH * TIW * PSTRIDE);   // IC4*9*DQ uint4
    int*     swf   = (int*)(dsm + TIH * TIW * PSTRIDE + IC4 * 9 * DQ * 16);

    const int tid = threadIdx.x;
    const int tilesY = H / TH;
    const int by = blockIdx.y % tilesY;
    const int b  = blockIdx.y / tilesY;
    const int cx0 = blockIdx.x * TW, cy0 = by * TH;
    const int oc0 = blockIdx.z * NOC;

    // load mma B-frags (MMAOC channels)
    for (int i = tid; i < 9 * CH * MMAOC * 8; i += 256) {
        const int p = i & 7, j = (i >> 3) % MMAOC, tc = (i >> 3) / MMAOC;
        swf[i] = wf[((tc * OC) + oc0 + j) * 8 + p];
    }
    // load dp4a weights
    {
        const uint4* dwz = dw + (long)blockIdx.z * (IC4 * 9 * DQ);
        for (int i = tid; i < IC4 * 9 * DQ; i += 256) sdw[i] = dwz[i];
    }
    // load input tile
    for (int i = tid; i < TIH * TIW * VPP; i += 256) {
        const int v = i % VPP, pix = i / VPP;
        const int gx = cx0 - 1 + pix % TIW;
        const int gy = cy0 - 1 + pix / TIW;
        uint4 val = make_uint4(0, 0, 0, 0);
        if (gx >= 0 && gx < H && gy >= 0 && gy < H)
            val = *(const uint4*)(xin + (((long)b * H + gy) * H + gx) * IC + v * 16);
        *(uint4*)(stile + pix * PSTRIDE + v * 16) = val;
    }
    __syncthreads();

    const int warp = tid >> 5, lane = tid & 31;
    const float combined = (__ldg(aprev_p) * (1.f / 3.f)) * get_scale(wtensor);
    const float alpha = __ldg(acur_p);
    const float inv_scale = 3.f / alpha;

    if (warp < 4) {
        // ---------------- mma path (tensor pipe) ----------------
        const uint32_t sbase = smem_u32(stile);
        const int r = lane >> 2;
        for (int wt = warp; wt < NWT; wt += 4) {
            const int tx = wt % WTX, ty = wt / WTX;
            const int piy = ty * 2 + ((lane >> 3) & 1);
            const int pix = tx * 8 + (lane & 7);
            const uint32_t abase = sbase + (piy * TIW + pix) * PSTRIDE
                                 + ((lane >> 4) << 4);
            int acc[OCG][4];
            #pragma unroll
            for (int g = 0; g < OCG; g++)
                #pragma unroll
                for (int q = 0; q < 4; q++) acc[g][q] = 0;

            #pragma unroll
            for (int t = 0; t < 9; t++) {
                const int dy = t / 3, dx = t % 3;
                #pragma unroll
                for (int c = 0; c < CH; c++) {
                    int a0, a1, a2, a3;
                    ldsm4(abase + (dy * TIW + dx) * PSTRIDE + c * 32,
                          a0, a1, a2, a3);
                    #pragma unroll
                    for (int g = 0; g < OCG; g++) {
                        const uint2 bb = *(const uint2*)
                            &swf[(((t * CH + c) * MMAOC) + g * 8 + (lane >> 2)) * 8
                                 + 2 * (lane & 3)];
                        mma_s8(acc[g], a0, a1, a2, a3, (int)bb.x, (int)bb.y);
                    }
                }
            }
            #pragma unroll
            for (int g = 0; g < OCG; g++) {
                const int v0 = max(acc[g][0], acc[g][2]);
                const int v1 = max(acc[g][1], acc[g][3]);
                const int o0 = max(v0, __shfl_xor_sync(0xffffffffu, v0, 4));
                const int o1 = max(v1, __shfl_xor_sync(0xffffffffu, v1, 4));
                if (!(r & 1)) {
                    const int ppx = (cx0 >> 1) + tx * 4 + (r >> 1);
                    const int ppy = (cy0 >> 1) + ty;
                    const float f0 = fminf(fmaxf((float)o0 * combined, 0.f), alpha);
                    const float f1 = fminf(fmaxf((float)o1 * combined, 0.f), alpha);
                    const uint32_t c0 = (uint32_t)(int)rintf(f0 * inv_scale);
                    const uint32_t c1 = (uint32_t)(int)rintf(f1 * inv_scale);
                    const int oc = oc0 + g * 8 + (lane & 3) * 2;
                    *(uint16_t*)(out + (((long)b * PHW + ppy) * PHW + ppx) * OC + oc)
                        = (uint16_t)(c0 | (c1 << 8));
                }
            }
        }
    } else {
        // ---------------- dp4a path (alu pipe), LDS.128 loads ----------------
        const int dt = tid - 128;              // 0..127
        const int cx = dt % TW, cyp = dt / TW;
        const bool active = dt < DLANES;
        const int dcyp = min(cyp, TH / 2 - 1);

        int acc[DPOC][2];
        #pragma unroll
        for (int j = 0; j < DPOC; j++) { acc[j][0] = 0; acc[j][1] = 0; }

        #pragma unroll 1
        for (int g4 = 0; g4 < IC16; g4++) {
            uint4 win[4][3];
            const uint8_t* tb = stile + ((2 * dcyp) * TIW + cx) * PSTRIDE
                              + g4 * 16;
            #pragma unroll
            for (int rr = 0; rr < 4; rr++)
                #pragma unroll
                for (int cc = 0; cc < 3; cc++)
                    win[rr][cc] = *(const uint4*)(tb + (rr * TIW + cc) * PSTRIDE);
            #pragma unroll
            for (int kk = 0; kk < 4; kk++) {
                const int k = g4 * 4 + kk;
                #pragma unroll
                for (int t = 0; t < 9; t++) {
                    const int dy = t / 3, dx = t % 3;
                    const uint32_t a0 =
                        ((const uint32_t*)&win[dy][dx])[kk];
                    const uint32_t a1 =
                        ((const uint32_t*)&win[dy + 1][dx])[kk];
                    #pragma unroll
                    for (int q = 0; q < DQ; q++) {
                        const uint4 w = sdw[(k * 9 + t) * DQ + q];
                        acc[q*4+0][0] = __dp4a((int)a0, (int)w.x, acc[q*4+0][0]);
                        acc[q*4+0][1] = __dp4a((int)a1, (int)w.x, acc[q*4+0][1]);
                        acc[q*4+1][0] = __dp4a((int)a0, (int)w.y, acc[q*4+1][0]);
                        acc[q*4+1][1] = __dp4a((int)a1, (int)w.y, acc[q*4+1][1]);
                        acc[q*4+2][0] = __dp4a((int)a0, (int)w.z, acc[q*4+2][0]);
                        acc[q*4+2][1] = __dp4a((int)a1, (int)w.z, acc[q*4+2][1]);
                        acc[q*4+3][0] = __dp4a((int)a0, (int)w.w, acc[q*4+3][0]);
                        acc[q*4+3][1] = __dp4a((int)a1, (int)w.w, acc[q*4+3][1]);
                    }
                }
            }
        }

        uint32_t pw[DQ];
        #pragma unroll
        for (int q = 0; q < DQ; q++) pw[q] = 0;
        #pragma unroll
        for (int j = 0; j < DPOC; j++) {
            int v = max(acc[j][0], acc[j][1]);        // vertical pool
            v = max(v, __shfl_xor_sync(0xffffffffu, v, 1));  // horizontal
            const float f = fminf(fmaxf((float)v * combined, 0.f), alpha);
            const uint32_t code = (uint32_t)(int)rintf(f * inv_scale);
            pw[j >> 2] |= code << (8 * (j & 3));
        }
        if (active && !(cx & 1)) {
            const int ppx = (cx0 >> 1) + (cx >> 1);
            const int ppy = (cy0 >> 1) + cyp;
            uint8_t* o = out + (((long)b * PHW + ppy) * PHW + ppx) * OC
                       + oc0 + MMAOC;
            ((uint2*)o)[0] = make_uint2(pw[0], pw[1]);
            ((uint2*)o)[1] = make_uint2(pw[2], pw[3]);
            ((uint2*)o)[2] = make_uint2(pw[4], pw[5]);
        }
    }
}

// ---- global max over 28x28 + 1x1 quantized conv classifier ------------------
__global__ void gmax_fc_kernel(const uint8_t* __restrict__ h3,
                               const float* __restrict__ a3_p,
                               float* __restrict__ out) {
    __shared__ uint32_t sm[4][32];
    __shared__ float gm[128];
    const int b = blockIdx.x;
    const int tid = threadIdx.x;
    const int w = tid >> 5, c4 = tid & 31;
    const uint32_t* p = (const uint32_t*)(h3 + (long)b * 784 * 128);
    uint32_t m = 0;
    for (int pix = w; pix < 784; pix += 4)
        m = __vmaxu4(m, p[(long)pix * 32 + c4]);
    sm[w][c4] = m;
    __syncthreads();
    if (tid < 32) {
        const uint32_t v = __vmaxu4(__vmaxu4(sm[0][tid], sm[1][tid]),
                                    __vmaxu4(sm[2][tid], sm[3][tid]));
        const float sc = __ldg(a3_p) * (1.f / 3.f);
        gm[tid * 4 + 0] = (float)(v & 0xff) * sc;
        gm[tid * 4 + 1] = (float)((v >> 8) & 0xff) * sc;
        gm[tid * 4 + 2] = (float)((v >> 16) & 0xff) * sc;
        gm[tid * 4 + 3] = (float)(v >> 24) * sc;
    }
    __syncthreads();
    if (tid < 10) {
        float s = 0.f;
        #pragma unroll 8
        for (int k = 0; k < 128; k++)
            s = fmaf(gm[k], g_qwc[tid * 128 + k], s);
        out[b * 10 + tid] = s;
    }
}

// ---------------------------------------------------------------------------
extern "C" void kernel_launch(void* const* d_in, const int* in_sizes, int n_in,
                              void* d_out, int out_size) {
    const float* x  = (const float*)d_in[0];
    const float* w1 = (const float*)d_in[1];
    const float* w2 = (const float*)d_in[2];
    const float* w3 = (const float*)d_in[3];
    const float* wc = (const float*)d_in[4];
    const float* a1 = (const float*)d_in[5];
    const float* a2 = (const float*)d_in[6];
    const float* a3 = (const float*)d_in[7];

    int *wf2, *wf3;
    uint4 *dw2, *dw3;
    uint8_t *c1, *c2, *c3;
    cudaGetSymbolAddress((void**)&wf2, g_wf2);
    cudaGetSymbolAddress((void**)&wf3, g_wf3);
    cudaGetSymbolAddress((void**)&dw2, g_dw2);
    cudaGetSymbolAddress((void**)&dw3, g_dw3);
    cudaGetSymbolAddress((void**)&c1, g_c1);
    cudaGetSymbolAddress((void**)&c2, g_c2);
    cudaGetSymbolAddress((void**)&c3, g_c3);

    // conv2: H=112, IC=32, CTA tile 16x16, mma 40 + dp4a 24 channels
    auto k2 = conv_hyb<112, 32, 64, 64, 40, 16, 16, 48>;
    constexpr int SM2 = 18 * 18 * 48 + 8 * 9 * 6 * 16 + 9 * 1 * 40 * 8 * 4;
    // conv3: H=56, IC=64, CTA tile 8x28, mma 40 + dp4a 24 of 64/CTA
    auto k3 = conv_hyb<56, 64, 128, 64, 40, 8, 28, 80>;
    constexpr int SM3 = 30 * 10 * 80 + 16 * 9 * 6 * 16 + 9 * 2 * 40 * 8 * 4;
    cudaFuncSetAttribute(k2, cudaFuncAttributeMaxDynamicSharedMemorySize, SM2);
    cudaFuncSetAttribute(k3, cudaFuncAttributeMaxDynamicSharedMemorySize, SM3);

    maxabs_kernel<<<22, 256>>>(w1, wc, w2, w3);
    pack_kernel<<<6, 256>>>(w1, wc, w2, w3);

    // block 1: [32,3,224,224] -> codes [32,112,112,32]
    conv1_kernel<<<dim3(7, 14 * 32, 4), 128>>>(x, a1, c1);
    // block 2: -> codes [32,56,56,64]
    k2<<<dim3(7, 7 * 32, 1), 256, SM2>>>(c1, wf2, dw2, a1, a2, 2, c2);
    // block 3: -> codes [32,28,28,128]
    k3<<<dim3(7, 2 * 32, 2), 256, SM3>>>(c2, wf3, dw3, a2, a3, 3, c3);

    // global max + classifier
    gmax_fc_kernel<<<32, 128>>>(c3, a3, (float*)d_out);
}

// round 8
// speedup vs baseline: 1.0071x; 1.0071x over previous
#include <cuda_runtime.h>
#include <cuda_bf16.h>
#include <stdint.h>
#include <math.h>

// ---------------------------------------------------------------------------
// 2-bit quantized CNN forward.
//  conv1: fp32 conv via packed fma.rn.f32x2
//  conv2/conv3: hybrid warp-specialized int8 conv:
//    warps 0-3: mma.sync.m16n8k32.s8 (tensor pipe) for 40/64 channels
//    warps 4-7: dp4a (alu pipe) for 24/64 channels, column-streamed LDS.128
//  Exact integer math: conv = (sum code*wint) * (alpha_prev/3 * s_w).
// ---------------------------------------------------------------------------

__device__ unsigned g_smax[4];                 // maxabs bits: w1, wc, w2, w3
__device__ float    g_qw1[32 * 3 * 9];
__device__ float    g_qwc[10 * 128];
__device__ int      g_wf2[9 * 64 * 8];         // mma B-frags [tap][oc][p]
__device__ int      g_wf3[9 * 2 * 128 * 8];    // [tap][chunk][oc][p]
__device__ uint4    g_dw2[8 * 9 * 6];          // dp4a w [k][tap][oc4] (oc40..63)
__device__ uint4    g_dw3[2 * 16 * 9 * 6];     // [z][k][tap][oc4]
__device__ uint8_t  g_c1[32L * 112 * 112 * 32];
__device__ uint8_t  g_c2[32L * 56 * 56 * 64];
__device__ uint8_t  g_c3[32L * 28 * 28 * 128];

// ---- helpers ---------------------------------------------------------------
__device__ __forceinline__ uint32_t smem_u32(const void* p) {
    uint32_t a;
    asm("{ .reg .u64 t; cvta.to.shared.u64 t, %1; cvt.u32.u64 %0, t; }"
        : "=r"(a) : "l"(p));
    return a;
}
__device__ __forceinline__ void ldsm4(uint32_t addr, int& a0, int& a1,
                                      int& a2, int& a3) {
    asm volatile("ldmatrix.sync.aligned.m8n8.x4.shared.b16 {%0,%1,%2,%3},[%4];"
                 : "=r"(a0), "=r"(a1), "=r"(a2), "=r"(a3) : "r"(addr));
}
__device__ __forceinline__ void mma_s8(int* d, int a0, int a1, int a2, int a3,
                                       int b0, int b1) {
    asm("mma.sync.aligned.m16n8k32.row.col.s32.s8.s8.s32 "
        "{%0,%1,%2,%3},{%4,%5,%6,%7},{%8,%9},{%0,%1,%2,%3};"
        : "+r"(d[0]), "+r"(d[1]), "+r"(d[2]), "+r"(d[3])
        : "r"(a0), "r"(a1), "r"(a2), "r"(a3), "r"(b0), "r"(b1));
}
#define PACK_F32X2(out, lo, hi) \
    asm("mov.b64 %0, {%1, %2};" : "=l"(out) : "r"(lo), "r"(hi))
#define UNPACK_F32X2(lo, hi, in) \
    asm("mov.b64 {%0, %1}, %2;" : "=f"(lo), "=f"(hi) : "l"(in))
#define FMA_F32X2(acc, a, b) \
    asm("fma.rn.f32x2 %0, %1, %2, %0;" : "+l"(acc) : "l"(a), "l"(b))

__device__ __forceinline__ float get_scale(int t) {
    return fmaxf(__uint_as_float(g_smax[t]), 1e-8f);
}

// ---- prologue 1: max|w| -----------------------------------------------------
__global__ void maxabs_kernel(const float* __restrict__ w1,
                              const float* __restrict__ wc,
                              const float* __restrict__ w2,
                              const float* __restrict__ w3) {
    __shared__ float red[8];
    const int blk = blockIdx.x;
    int t, base, cnt;
    const float* p;
    if (blk == 0)      { t = 0; p = w1; base = 0; cnt = 864; }
    else if (blk == 1) { t = 1; p = wc; base = 0; cnt = 1280; }
    else if (blk < 6)  { t = 2; p = w2; base = (blk - 2) * 4608; cnt = 4608; }
    else               { t = 3; p = w3; base = (blk - 6) * 4608; cnt = 4608; }
    float m = 0.f;
    for (int i = threadIdx.x; i < cnt; i += 256)
        m = fmaxf(m, fabsf(p[base + i]));
    #pragma unroll
    for (int o = 16; o; o >>= 1)
        m = fmaxf(m, __shfl_xor_sync(0xffffffffu, m, o));
    if ((threadIdx.x & 31) == 0) red[threadIdx.x >> 5] = m;
    __syncthreads();
    if (threadIdx.x == 0) {
        float v = red[0];
        #pragma unroll
        for (int i = 1; i < 8; i++) v = fmaxf(v, red[i]);
        atomicMax(&g_smax[t], __float_as_uint(v));  // |w|>=0, bit-monotone
    }
}

// ---- prologue 2: quantize + pack --------------------------------------------
__global__ void pack_kernel(const float* __restrict__ w1,
                            const float* __restrict__ wc,
                            const float* __restrict__ w2,
                            const float* __restrict__ w3) {
    const int blk = blockIdx.x;
    if (blk == 0) {
        const float s = get_scale(0);
        for (int i = threadIdx.x; i < 864; i += 256)
            g_qw1[i] = rintf(w1[i] / s) * s;
    } else if (blk == 1) {
        const float s = get_scale(1);
        for (int i = threadIdx.x; i < 1280; i += 256)
            g_qwc[i] = rintf(wc[i] / s) * s;
    } else if (blk == 2) {
        // mma frags conv2: word p: icw = (p>>1) + (p&1)*4
        const float inv_s = 1.f / get_scale(2);
        for (int i = threadIdx.x; i < 9 * 64 * 8; i += 256) {
            const int tap = i / 512, r = i % 512, oc = r >> 3, p = r & 7;
            const int icw = (p >> 1) + ((p & 1) << 2);
            uint32_t word = 0;
            #pragma unroll
            for (int l = 0; l < 4; l++) {
                const int ic = icw * 4 + l;
                const int c = (int)rintf(w2[(oc * 32 + ic) * 9 + tap] * inv_s);
                word |= ((uint32_t)(uint8_t)(int8_t)c) << (8 * l);
            }
            g_wf2[i] = (int)word;
        }
    } else if (blk == 3) {
        const float inv_s = 1.f / get_scale(3);
        for (int i = threadIdx.x; i < 9 * 2 * 128 * 8; i += 256) {
            const int tap = i / 2048, r = i % 2048;
            const int chunk = r >> 10, r2 = r & 1023, oc = r2 >> 3, p = r2 & 7;
            const int icw = (p >> 1) + ((p & 1) << 2);
            uint32_t word = 0;
            #pragma unroll
            for (int l = 0; l < 4; l++) {
                const int ic = chunk * 32 + (icw * 4) + l;
                const int c = (int)rintf(w3[(oc * 64 + ic) * 9 + tap] * inv_s);
                word |= ((uint32_t)(uint8_t)(int8_t)c) << (8 * l);
            }
            g_wf3[i] = (int)word;
        }
    } else if (blk == 4) {
        // dp4a conv2 weights: oc 40..63, [k][tap][d] u32 words
        const float inv_s = 1.f / get_scale(2);
        uint32_t* dst = (uint32_t*)g_dw2;
        for (int i = threadIdx.x; i < 8 * 9 * 24; i += 256) {
            const int k = i / 216, t = (i % 216) / 24, d = i % 24;
            const int oc = 40 + d;
            uint32_t word = 0;
            #pragma unroll
            for (int l = 0; l < 4; l++) {
                const int ic = k * 4 + l;
                const int c = (int)rintf(w2[(oc * 32 + ic) * 9 + t] * inv_s);
                word |= ((uint32_t)(uint8_t)(int8_t)c) << (8 * l);
            }
            dst[i] = word;
        }
    } else {
        // dp4a conv3 weights: z in {0,1}, oc z*64+40..+63
        const float inv_s = 1.f / get_scale(3);
        uint32_t* dst = (uint32_t*)g_dw3;
        for (int i = threadIdx.x; i < 2 * 16 * 9 * 24; i += 256) {
            const int z = i / 3456, r = i % 3456;
            const int k = r / 216, t = (r % 216) / 24, d = r % 24;
            const int oc = z * 64 + 40 + d;
            uint32_t word = 0;
            #pragma unroll
            for (int l = 0; l < 4; l++) {
                const int ic = k * 4 + l;
                const int c = (int)rintf(w3[(oc * 64 + ic) * 9 + t] * inv_s);
                word |= ((uint32_t)(uint8_t)(int8_t)c) << (8 * l);
            }
            dst[i] = word;
        }
    }
}

// ---- block 1: fp32 conv3x3(pad1) via fma.f32x2 + quant_act + maxpool2 -------
__global__ __launch_bounds__(128) void conv1_kernel(
    const float* __restrict__ x, const float* __restrict__ alpha_p,
    uint8_t* __restrict__ out) {
    constexpr int H = 224, W = 224, PH = 112, PW = 112, OC = 32, OCB = 8;
    __shared__ float sx[3][18][34];
    __shared__ unsigned long long swp[OCB][3][9];   // (w,w) duplicated pairs

    const int tid = threadIdx.x;
    const int tx = tid & 15, ty = tid >> 4;
    const int tile_x = blockIdx.x;
    const int tile_y = blockIdx.y % 14;
    const int b      = blockIdx.y / 14;
    const int oc0    = blockIdx.z * OCB;

    const int px0 = tile_x * 16, py0 = tile_y * 8;
    const int ix0 = 2 * px0 - 1, iy0 = 2 * py0 - 1;

    const float* xb = x + (long)b * 3 * H * W;
    for (int i = tid; i < 3 * 18 * 34; i += 128) {
        const int ic = i / 612, rr = (i % 612) / 34, cc = i % 34;
        const int gy = iy0 + rr, gx = ix0 + cc;
        float v = 0.f;
        if (gy >= 0 && gy < H && gx >= 0 && gx < W)
            v = xb[(long)ic * H * W + gy * W + gx];
        sx[ic][rr][cc] = v;
    }
    if (tid < OCB * 27) {
        const int j = tid / 27, r27 = tid % 27;
        const float w = g_qw1[((oc0 + j) * 3 + r27 / 9) * 9 + r27 % 9];
        unsigned long long pw;
        PACK_F32X2(pw, __float_as_uint(w), __float_as_uint(w));
        swp[j][r27 / 9][r27 % 9] = pw;
    }
    __syncthreads();

    unsigned long long accA[OCB], accB[OCB];
    #pragma unroll
    for (int j = 0; j < OCB; j++) { accA[j] = 0ull; accB[j] = 0ull; }

    #pragma unroll
    for (int ic = 0; ic < 3; ic++) {
        float win[4][4];
        #pragma unroll
        for (int r = 0; r < 4; r++)
            #pragma unroll
            for (int c = 0; c < 4; c++)
                win[r][c] = sx[ic][2 * ty + r][2 * tx + c];
        unsigned long long pk[4][3];
        #pragma unroll
        for (int r = 0; r < 4; r++)
            #pragma unroll
            for (int c = 0; c < 3; c++)
                PACK_F32X2(pk[r][c], __float_as_uint(win[r][c]),
                           __float_as_uint(win[r][c + 1]));
        #pragma unroll
        for (int j = 0; j < OCB; j++) {
            #pragma unroll
            for (int ky = 0; ky < 3; ky++)
                #pragma unroll
                for (int kx = 0; kx < 3; kx++) {
                    FMA_F32X2(accA[j], pk[ky][kx], swp[j][ic][ky * 3 + kx]);
                    FMA_F32X2(accB[j], pk[ky + 1][kx], swp[j][ic][ky * 3 + kx]);
                }
        }
    }

    const float alpha = __ldg(alpha_p);
    const float inv_scale = 3.f / alpha;
    const int px = px0 + tx, py = py0 + ty;
    uint32_t lo = 0, hi = 0;
    #pragma unroll
    for (int j = 0; j < OCB; j++) {
        float p0, p1, p2, p3;
        UNPACK_F32X2(p0, p1, accA[j]);
        UNPACK_F32X2(p2, p3, accB[j]);
        const float m = fmaxf(fmaxf(p0, p1), fmaxf(p2, p3));
        const float y = fminf(fmaxf(m, 0.f), alpha);
        const uint32_t code = (uint32_t)(int)rintf(y * inv_scale);
        if (j < 4) lo |= code << (8 * j);
        else       hi |= code << (8 * (j - 4));
    }
    *(uint2*)&out[(((long)b * PH + py) * PW + px) * OC + oc0] = make_uint2(lo, hi);
}

// ---- blocks 2/3: hybrid mma+dp4a conv + quant_act + maxpool2 ----------------
// 8 warps: warps 0-3 = mma (MMAOC channels), warps 4-7 = dp4a (DPOC channels).
// dp4a path streams ONE tap-column of 4 rows at a time (col[4] uint4 = 16
// regs live instead of win[4][3] = 48) -> no register spills.
template <int H, int IC, int OC, int NOC, int MMAOC, int TW, int TH, int PSTRIDE>
__global__ __launch_bounds__(256) void conv_hyb(
    const uint8_t* __restrict__ xin, const int* __restrict__ wf,
    const uint4* __restrict__ dw,
    const float* __restrict__ aprev_p, const float* __restrict__ acur_p,
    int wtensor, uint8_t* __restrict__ out) {
    constexpr int DPOC = NOC - MMAOC;          // 24
    constexpr int DQ   = DPOC / 4;             // 6
    constexpr int CH   = IC / 32;
    constexpr int IC4  = IC / 4;
    constexpr int IC16 = IC / 16;              // uint4 k-groups
    constexpr int TIW  = TW + 2, TIH = TH + 2;
    constexpr int OCG  = MMAOC / 8;            // 5
    constexpr int VPP  = IC / 16;
    constexpr int WTX  = TW / 8, WTY = TH / 2, NWT = WTX * WTY;
    constexpr int PHW  = H / 2;
    constexpr int DLANES = TW * (TH / 2);

    extern __shared__ __align__(16) uint8_t dsm[];
    uint8_t* stile = dsm;                                   // TIH*TIW*PSTRIDE
    uint4*   sdw   = (uint4*)(dsm + TIH * TIW * PSTRIDE);   // IC4*9*DQ uint4
    int*     swf   = (int*)(dsm + TIH * TIW * PSTRIDE + IC4 * 9 * DQ * 16);

    const int tid = threadIdx.x;
    const int tilesY = H / TH;
    const int by = blockIdx.y % tilesY;
    const int b  = blockIdx.y / tilesY;
    const int cx0 = blockIdx.x * TW, cy0 = by * TH;
    const int oc0 = blockIdx.z * NOC;

    // load mma B-frags (MMAOC channels)
    for (int i = tid; i < 9 * CH * MMAOC * 8; i += 256) {
        const int p = i & 7, j = (i >> 3) % MMAOC, tc = (i >> 3) / MMAOC;
        swf[i] = wf[((tc * OC) + oc0 + j) * 8 + p];
    }
    // load dp4a weights
    {
        const uint4* dwz = dw + (long)blockIdx.z * (IC4 * 9 * DQ);
        for (int i = tid; i < IC4 * 9 * DQ; i += 256) sdw[i] = dwz[i];
    }
    // load input tile
    for (int i = tid; i < TIH * TIW * VPP; i += 256) {
        const int v = i % VPP, pix = i / VPP;
        const int gx = cx0 - 1 + pix % TIW;
        const int gy = cy0 - 1 + pix / TIW;
        uint4 val = make_uint4(0, 0, 0, 0);
        if (gx >= 0 && gx < H && gy >= 0 && gy < H)
            val = *(const uint4*)(xin + (((long)b * H + gy) * H + gx) * IC + v * 16);
        *(uint4*)(stile + pix * PSTRIDE + v * 16) = val;
    }
    __syncthreads();

    const int warp = tid >> 5, lane = tid & 31;
    const float combined = (__ldg(aprev_p) * (1.f / 3.f)) * get_scale(wtensor);
    const float alpha = __ldg(acur_p);
    const float inv_scale = 3.f / alpha;

    if (warp < 4) {
        // ---------------- mma path (tensor pipe) ----------------
        const uint32_t sbase = smem_u32(stile);
        const int r = lane >> 2;
        for (int wt = warp; wt < NWT; wt += 4) {
            const int tx = wt % WTX, ty = wt / WTX;
            const int piy = ty * 2 + ((lane >> 3) & 1);
            const int pix = tx * 8 + (lane & 7);
            const uint32_t abase = sbase + (piy * TIW + pix) * PSTRIDE
                                 + ((lane >> 4) << 4);
            int acc[OCG][4];
            #pragma unroll
            for (int g = 0; g < OCG; g++)
                #pragma unroll
                for (int q = 0; q < 4; q++) acc[g][q] = 0;

            #pragma unroll
            for (int t = 0; t < 9; t++) {
                const int dy = t / 3, dx = t % 3;
                #pragma unroll
                for (int c = 0; c < CH; c++) {
                    int a0, a1, a2, a3;
                    ldsm4(abase + (dy * TIW + dx) * PSTRIDE + c * 32,
                          a0, a1, a2, a3);
                    #pragma unroll
                    for (int g = 0; g < OCG; g++) {
                        const uint2 bb = *(const uint2*)
                            &swf[(((t * CH + c) * MMAOC) + g * 8 + (lane >> 2)) * 8
                                 + 2 * (lane & 3)];
                        mma_s8(acc[g], a0, a1, a2, a3, (int)bb.x, (int)bb.y);
                    }
                }
            }
            #pragma unroll
            for (int g = 0; g < OCG; g++) {
                const int v0 = max(acc[g][0], acc[g][2]);
                const int v1 = max(acc[g][1], acc[g][3]);
                const int o0 = max(v0, __shfl_xor_sync(0xffffffffu, v0, 4));
                const int o1 = max(v1, __shfl_xor_sync(0xffffffffu, v1, 4));
                if (!(r & 1)) {
                    const int ppx = (cx0 >> 1) + tx * 4 + (r >> 1);
                    const int ppy = (cy0 >> 1) + ty;
                    const float f0 = fminf(fmaxf((float)o0 * combined, 0.f), alpha);
                    const float f1 = fminf(fmaxf((float)o1 * combined, 0.f), alpha);
                    const uint32_t c0 = (uint32_t)(int)rintf(f0 * inv_scale);
                    const uint32_t c1 = (uint32_t)(int)rintf(f1 * inv_scale);
                    const int oc = oc0 + g * 8 + (lane & 3) * 2;
                    *(uint16_t*)(out + (((long)b * PHW + ppy) * PHW + ppx) * OC + oc)
                        = (uint16_t)(c0 | (c1 << 8));
                }
            }
        }
    } else {
        // -------- dp4a path (alu pipe), column-streamed LDS.128 --------
        const int dt = tid - 128;              // 0..127
        const int cx = dt % TW, cyp = dt / TW;
        const bool active = dt < DLANES;
        const int dcyp = min(cyp, TH / 2 - 1);

        int acc[DPOC][2];
        #pragma unroll
        for (int j = 0; j < DPOC; j++) { acc[j][0] = 0; acc[j][1] = 0; }

        #pragma unroll 1
        for (int g4 = 0; g4 < IC16; g4++) {
            const uint8_t* tb = stile + ((2 * dcyp) * TIW + cx) * PSTRIDE
                              + g4 * 16;
            #pragma unroll
            for (int cc = 0; cc < 3; cc++) {
                uint4 col[4];
                #pragma unroll
                for (int rr = 0; rr < 4; rr++)
                    col[rr] = *(const uint4*)(tb + (rr * TIW + cc) * PSTRIDE);
                #pragma unroll
                for (int dy = 0; dy < 3; dy++) {
                    const int t = dy * 3 + cc;
                    #pragma unroll
                    for (int kk = 0; kk < 4; kk++) {
                        const uint32_t a0 = ((const uint32_t*)&col[dy])[kk];
                        const uint32_t a1 = ((const uint32_t*)&col[dy + 1])[kk];
                        const int k = g4 * 4 + kk;
                        #pragma unroll
                        for (int q = 0; q < DQ; q++) {
                            const uint4 w = sdw[(k * 9 + t) * DQ + q];
                            acc[q*4+0][0] = __dp4a((int)a0, (int)w.x, acc[q*4+0][0]);
                            acc[q*4+0][1] = __dp4a((int)a1, (int)w.x, acc[q*4+0][1]);
                            acc[q*4+1][0] = __dp4a((int)a0, (int)w.y, acc[q*4+1][0]);
                            acc[q*4+1][1] = __dp4a((int)a1, (int)w.y, acc[q*4+1][1]);
                            acc[q*4+2][0] = __dp4a((int)a0, (int)w.z, acc[q*4+2][0]);
                            acc[q*4+2][1] = __dp4a((int)a1, (int)w.z, acc[q*4+2][1]);
                            acc[q*4+3][0] = __dp4a((int)a0, (int)w.w, acc[q*4+3][0]);
                            acc[q*4+3][1] = __dp4a((int)a1, (int)w.w, acc[q*4+3][1]);
                        }
                    }
                }
            }
        }

        uint32_t pw[DQ];
        #pragma unroll
        for (int q = 0; q < DQ; q++) pw[q] = 0;
        #pragma unroll
        for (int j = 0; j < DPOC; j++) {
            int v = max(acc[j][0], acc[j][1]);        // vertical pool
            v = max(v, __shfl_xor_sync(0xffffffffu, v, 1));  // horizontal
            const float f = fminf(fmaxf((float)v * combined, 0.f), alpha);
            const uint32_t code = (uint32_t)(int)rintf(f * inv_scale);
            pw[j >> 2] |= code << (8 * (j & 3));
        }
        if (active && !(cx & 1)) {
            const int ppx = (cx0 >> 1) + (cx >> 1);
            const int ppy = (cy0 >> 1) + cyp;
            uint8_t* o = out + (((long)b * PHW + ppy) * PHW + ppx) * OC
                       + oc0 + MMAOC;
            ((uint2*)o)[0] = make_uint2(pw[0], pw[1]);
            ((uint2*)o)[1] = make_uint2(pw[2], pw[3]);
            ((uint2*)o)[2] = make_uint2(pw[4], pw[5]);
        }
    }
}

// ---- global max over 28x28 + 1x1 quantized conv classifier ------------------
__global__ void gmax_fc_kernel(const uint8_t* __restrict__ h3,
                               const float* __restrict__ a3_p,
                               float* __restrict__ out) {
    __shared__ uint32_t sm[4][32];
    __shared__ float gm[128];
    const int b = blockIdx.x;
    const int tid = threadIdx.x;
    const int w = tid >> 5, c4 = tid & 31;
    const uint32_t* p = (const uint32_t*)(h3 + (long)b * 784 * 128);
    uint32_t m = 0;
    for (int pix = w; pix < 784; pix += 4)
        m = __vmaxu4(m, p[(long)pix * 32 + c4]);
    sm[w][c4] = m;
    __syncthreads();
    if (tid < 32) {
        const uint32_t v = __vmaxu4(__vmaxu4(sm[0][tid], sm[1][tid]),
                                    __vmaxu4(sm[2][tid], sm[3][tid]));
        const float sc = __ldg(a3_p) * (1.f / 3.f);
        gm[tid * 4 + 0] = (float)(v & 0xff) * sc;
        gm[tid * 4 + 1] = (float)((v >> 8) & 0xff) * sc;
        gm[tid * 4 + 2] = (float)((v >> 16) & 0xff) * sc;
        gm[tid * 4 + 3] = (float)(v >> 24) * sc;
    }
    __syncthreads();
    if (tid < 10) {
        float s = 0.f;
        #pragma unroll 8
        for (int k = 0; k < 128; k++)
            s = fmaf(gm[k], g_qwc[tid * 128 + k], s);
        out[b * 10 + tid] = s;
    }
}

// ---------------------------------------------------------------------------
extern "C" void kernel_launch(void* const* d_in, const int* in_sizes, int n_in,
                              void* d_out, int out_size) {
    const float* x  = (const float*)d_in[0];
    const float* w1 = (const float*)d_in[1];
    const float* w2 = (const float*)d_in[2];
    const float* w3 = (const float*)d_in[3];
    const float* wc = (const float*)d_in[4];
    const float* a1 = (const float*)d_in[5];
    const float* a2 = (const float*)d_in[6];
    const float* a3 = (const float*)d_in[7];

    int *wf2, *wf3;
    uint4 *dw2, *dw3;
    uint8_t *c1, *c2, *c3;
    cudaGetSymbolAddress((void**)&wf2, g_wf2);
    cudaGetSymbolAddress((void**)&wf3, g_wf3);
    cudaGetSymbolAddress((void**)&dw2, g_dw2);
    cudaGetSymbolAddress((void**)&dw3, g_dw3);
    cudaGetSymbolAddress((void**)&c1, g_c1);
    cudaGetSymbolAddress((void**)&c2, g_c2);
    cudaGetSymbolAddress((void**)&c3, g_c3);

    // conv2: H=112, IC=32, CTA tile 16x16, mma 40 + dp4a 24 channels
    auto k2 = conv_hyb<112, 32, 64, 64, 40, 16, 16, 48>;
    constexpr int SM2 = 18 * 18 * 48 + 8 * 9 * 6 * 16 + 9 * 1 * 40 * 8 * 4;
    // conv3: H=56, IC=64, CTA tile 8x28, mma 40 + dp4a 24 of 64/CTA
    auto k3 = conv_hyb<56, 64, 128, 64, 40, 8, 28, 80>;
    constexpr int SM3 = 30 * 10 * 80 + 16 * 9 * 6 * 16 + 9 * 2 * 40 * 8 * 4;
    cudaFuncSetAttribute(k2, cudaFuncAttributeMaxDynamicSharedMemorySize, SM2);
    cudaFuncSetAttribute(k3, cudaFuncAttributeMaxDynamicSharedMemorySize, SM3);

    maxabs_kernel<<<22, 256>>>(w1, wc, w2, w3);
    pack_kernel<<<6, 256>>>(w1, wc, w2, w3);

    // block 1: [32,3,224,224] -> codes [32,112,112,32]
    conv1_kernel<<<dim3(7, 14 * 32, 4), 128>>>(x, a1, c1);
    // block 2: -> codes [32,56,56,64]
    k2<<<dim3(7, 7 * 32, 1), 256, SM2>>>(c1, wf2, dw2, a1, a2, 2, c2);
    // block 3: -> codes [32,28,28,128]
    k3<<<dim3(7, 2 * 32, 2), 256, SM3>>>(c2, wf3, dw3, a2, a3, 3, c3);

    // global max + classifier
    gmax_fc_kernel<<<32, 128>>>(c3, a3, (float*)d_out);
}